// round 15
// baseline (speedup 1.0000x reference)
#include <cuda_runtime.h>
#include <cuda_bf16.h>
#include <cstdint>

#define BATCH   4
#define SEQL    4096
#define DMODEL  2048
#define HALF    32
#define N2      64
#define MTOT    (BATCH*SEQL)
#define SCHUNK  32               // scan chunk length
#define NCH     (SEQL/SCHUNK)    // 128 chunks per batch

// ---------------- scratch ----------------
__device__ __nv_bfloat16 g_W1h[N2 * DMODEL];   // [j][d]  B operand of GEMM1
__device__ __nv_bfloat16 g_W1l[N2 * DMODEL];
__device__ __nv_bfloat16 g_W2h[DMODEL * N2];   // [d][j]  B operand of GEMM2
__device__ __nv_bfloat16 g_W2l[DMODEL * N2];
__device__ float g_Bu[MTOT * N2];
__device__ __nv_bfloat16 g_Xh[MTOT * N2];      // corrected X, bf16 hi
__device__ __nv_bfloat16 g_Xl[MTOT * N2];      // corrected X, bf16 lo
__device__ float g_car[BATCH * NCH * N2];      // chunk carries
__device__ float g_pre[BATCH * NCH * N2];      // exclusive chunk prefixes

// ---------------- helpers ----------------
__device__ __forceinline__ uint32_t smem_u32(const void* p) {
    uint32_t a;
    asm("{ .reg .u64 t; cvta.to.shared.u64 t, %1; cvt.u32.u64 %0, t; }"
        : "=r"(a) : "l"(p));
    return a;
}

__device__ __forceinline__ void cvt_hl(float x, uint16_t& h, uint16_t& l) {
    __nv_bfloat16 hb = __float2bfloat16_rn(x);
    float r = x - __bfloat162float(hb);
    __nv_bfloat16 lb = __float2bfloat16_rn(r);
    h = *(uint16_t*)&hb;
    l = *(uint16_t*)&lb;
}

// paired split: 2 floats -> packed bf16x2 hi + packed bf16x2 lo
__device__ __forceinline__ void cvt_hl2(float x0, float x1,
                                        uint32_t& h, uint32_t& l) {
    uint32_t hp;
    asm("cvt.rn.bf16x2.f32 %0, %1, %2;" : "=r"(hp) : "f"(x1), "f"(x0));
    float f0 = __uint_as_float(hp << 16);
    float f1 = __uint_as_float(hp & 0xffff0000u);
    float r0 = x0 - f0;
    float r1 = x1 - f1;
    asm("cvt.rn.bf16x2.f32 %0, %1, %2;" : "=r"(l) : "f"(r1), "f"(r0));
    h = hp;
}

__device__ __forceinline__ void cvt8(const float4& v0, const float4& v1,
                                     uint4& h, uint4& l) {
    cvt_hl2(v0.x, v0.y, h.x, l.x);
    cvt_hl2(v0.z, v0.w, h.y, l.y);
    cvt_hl2(v1.x, v1.y, h.z, l.z);
    cvt_hl2(v1.z, v1.w, h.w, l.w);
}

__device__ __forceinline__ void mma16816(float* c, const uint32_t* a,
                                         const uint32_t* b) {
    asm volatile(
        "mma.sync.aligned.m16n8k16.row.col.f32.bf16.bf16.f32 "
        "{%0,%1,%2,%3}, {%4,%5,%6,%7}, {%8,%9}, {%0,%1,%2,%3};"
        : "+f"(c[0]), "+f"(c[1]), "+f"(c[2]), "+f"(c[3])
        : "r"(a[0]), "r"(a[1]), "r"(a[2]), "r"(a[3]), "r"(b[0]), "r"(b[1]));
}

__device__ __forceinline__ void ldsm4(uint32_t addr, uint32_t* r) {
    asm volatile(
        "ldmatrix.sync.aligned.m8n8.x4.shared.b16 {%0,%1,%2,%3}, [%4];"
        : "=r"(r[0]), "=r"(r[1]), "=r"(r[2]), "=r"(r[3]) : "r"(addr));
}

// Panels: kp holds 8 k-values; 16B per row; XOR(row, kp) swizzle.
__device__ __forceinline__ uint32_t lmoff(int p, int rb, int lane, int psz) {
    int pp = p + (lane >> 4);
    int row = rb + (lane & 15);
    return (uint32_t)(pp * psz + (((row ^ (pp & 7)) << 4)));
}

// per-state discrete params
__device__ __forceinline__ void lam_bar(const float* Lur, const float* Lim,
                                        const float* logD, int n,
                                        float& lbr, float& lbi,
                                        float& ar, float& ai) {
    float x   = Lur[n];
    float sp  = (x > 20.f) ? x : log1pf(expf(x));
    float lre = -(sp + 1e-4f + 0.01f);
    float lim = Lim[n];
    float dt  = expf(logD[n]);
    ar = lre * dt; ai = lim * dt;
    float er = expf(ar);
    lbr = er * cosf(ai);
    lbi = er * sinf(ai);
}

// ---------------- fused weight prep ----------------
__global__ void k_wprep(const float* __restrict__ Lur,
                        const float* __restrict__ Lim,
                        const float* __restrict__ logD,
                        const float* __restrict__ Bre,
                        const float* __restrict__ Bim,
                        const float* __restrict__ Cre,
                        const float* __restrict__ Cim) {
    __shared__ float s_sre[HALF], s_sim[HALF];
    if (threadIdx.x < HALF) {
        int n = threadIdx.x;
        float lbr, lbi, ar, ai;
        lam_bar(Lur, Lim, logD, n, lbr, lbi, ar, ai);
        float x   = Lur[n];
        float sp  = (x > 20.f) ? x : log1pf(expf(x));
        float lre = -(sp + 1e-4f + 0.01f);
        float lim = Lim[n];
        float den = lre * lre + lim * lim;
        float nr = lbr - 1.f, ni = lbi;
        s_sre[n] = (nr * lre + ni * lim) / den;
        s_sim[n] = (ni * lre - nr * lim) / den;
    }
    __syncthreads();
    const int total = N2 * DMODEL;
    for (int idx = blockIdx.x * blockDim.x + threadIdx.x; idx < total;
         idx += gridDim.x * blockDim.x) {
        {
            int j = idx >> 11;
            int d = idx & 2047;
            int n = j & 31;
            float br = Bre[n * DMODEL + d], bi = Bim[n * DMODEL + d];
            float v = (j < 32) ? (s_sre[n] * br - s_sim[n] * bi)
                               : (s_sre[n] * bi + s_sim[n] * br);
            uint16_t h, l;
            cvt_hl(v, h, l);
            g_W1h[idx] = *(__nv_bfloat16*)&h;
            g_W1l[idx] = *(__nv_bfloat16*)&l;
        }
        {
            int d = idx >> 6;
            int j = idx & 63;
            float v = (j < 32) ? (2.f * Cre[d * HALF + j])
                               : (-2.f * Cim[d * HALF + (j - 32)]);
            uint16_t h, l;
            cvt_hl(v, h, l);
            g_W2h[idx] = *(__nv_bfloat16*)&h;
            g_W2l[idx] = *(__nv_bfloat16*)&l;
        }
    }
}

// ---------------- GEMM1: BM=64, 128 thr (4 warps m32xn32), 3 CTAs/SM ----------
// Stage: Ah 8K | Al 8K | Bh 8K | Bl 8K = 32 KB, 2 stages (64 KB dynamic).
#define G1_STAGE 32768
__global__ __launch_bounds__(128) void k_gemm1(const float* __restrict__ u) {
    extern __shared__ char smem[];
    int tid = threadIdx.x;
    int lane = tid & 31, g = lane >> 2, tig = lane & 3;
    int w = tid >> 5, wm = w >> 1, wn = w & 1;     // 2x2 warps over 64x64
    int m0 = blockIdx.x * 64;

    float acc[2][4][4];
    #pragma unroll
    for (int mt = 0; mt < 2; ++mt)
        #pragma unroll
        for (int f = 0; f < 4; ++f)
            #pragma unroll
            for (int i = 0; i < 4; ++i) acc[mt][f][i] = 0.f;

    // compressed LDSM offsets (rows +16 => +256B; Al=Ah+8192; Bl=Bh+8192)
    uint32_t oA[4], oB[4];
    #pragma unroll
    for (int ks = 0; ks < 4; ++ks) {
        oA[ks] =         lmoff(ks * 2, wm * 32, lane, 1024);
        oB[ks] = 16384 + lmoff(ks * 2, wn * 32, lane, 1024);
    }
    uint32_t sb0 = smem_u32(smem);
    uint32_t sb1 = sb0 + G1_STAGE;

    float4 ru[4][2];
    uint4 rwh[4], rwl[4];

    #define G1_LDG(kb)                                                        \
        _Pragma("unroll")                                                     \
        for (int i = 0; i < 4; ++i) {                                         \
            int task = tid + 128 * i;                                         \
            int row = task >> 3, kp = task & 7;                               \
            const float* s = u + (size_t)(m0 + row) * DMODEL + (kb) + kp * 8; \
            ru[i][0] = *(const float4*)s;                                     \
            ru[i][1] = *(const float4*)(s + 4);                               \
        }                                                                     \
        _Pragma("unroll")                                                     \
        for (int i = 0; i < 4; ++i) {                                         \
            int task = tid + 128 * i;                                         \
            int n = task >> 3, kp = task & 7;                                 \
            size_t off = ((size_t)n * DMODEL + (kb) + kp * 8) * 2;            \
            rwh[i] = *(const uint4*)((const char*)g_W1h + off);               \
            rwl[i] = *(const uint4*)((const char*)g_W1l + off);               \
        }

    #define G1_STS(sbase)                                                     \
        _Pragma("unroll")                                                     \
        for (int i = 0; i < 4; ++i) {                                         \
            int task = tid + 128 * i;                                         \
            int row = task >> 3, kp = task & 7;                               \
            uint4 h, l;                                                       \
            cvt8(ru[i][0], ru[i][1], h, l);                                   \
            int off = kp * 1024 + ((row ^ kp) << 4);                          \
            *(uint4*)((sbase) + off) = h;                                     \
            *(uint4*)((sbase) + 8192 + off) = l;                              \
        }                                                                     \
        _Pragma("unroll")                                                     \
        for (int i = 0; i < 4; ++i) {                                         \
            int task = tid + 128 * i;                                         \
            int n = task >> 3, kp = task & 7;                                 \
            int off = kp * 1024 + ((n ^ kp) << 4);                            \
            *(uint4*)((sbase) + 16384 + off) = rwh[i];                        \
            *(uint4*)((sbase) + 24576 + off) = rwl[i];                        \
        }

    G1_LDG(0);
    G1_STS(smem);
    G1_LDG(64);
    __syncthreads();

    for (int kt = 0; kt < DMODEL / 64; ++kt) {
        if (kt + 1 < DMODEL / 64) {
            char* nst = smem + ((kt + 1) & 1) * G1_STAGE;
            G1_STS(nst);
        }
        if (kt + 2 < DMODEL / 64) {
            G1_LDG((kt + 2) * 64);
        }
        uint32_t sb = (kt & 1) ? sb1 : sb0;
        #pragma unroll
        for (int ks = 0; ks < 4; ++ks) {
            uint32_t a0 = sb + oA[ks];
            uint32_t b0 = sb + oB[ks];
            uint32_t ah0[4], ah1[4], al0[4], al1[4];
            ldsm4(a0,               ah0);
            ldsm4(a0 + 256,         ah1);
            ldsm4(a0 + 8192,        al0);
            ldsm4(a0 + 8192 + 256,  al1);
            uint32_t bh[8], bl[8];
            ldsm4(b0,               bh);
            ldsm4(b0 + 256,         bh + 4);
            ldsm4(b0 + 8192,        bl);
            ldsm4(b0 + 8192 + 256,  bl + 4);
            #pragma unroll
            for (int f = 0; f < 4; ++f) {
                int q = (f >> 1) * 4 + (f & 1);
                uint32_t bfh[2] = { bh[q], bh[q + 2] };
                uint32_t bfl[2] = { bl[q], bl[q + 2] };
                mma16816(acc[0][f], ah0, bfh);
                mma16816(acc[0][f], ah0, bfl);
                mma16816(acc[0][f], al0, bfh);
                mma16816(acc[1][f], ah1, bfh);
                mma16816(acc[1][f], ah1, bfl);
                mma16816(acc[1][f], al1, bfh);
            }
        }
        __syncthreads();
    }
    #pragma unroll
    for (int mt = 0; mt < 2; ++mt) {
        int r0 = m0 + wm * 32 + mt * 16 + g;
        #pragma unroll
        for (int f = 0; f < 4; ++f) {
            int col = wn * 32 + f * 8 + 2 * tig;
            float* a = acc[mt][f];
            *(float2*)(g_Bu + (size_t)r0 * N2 + col)       = make_float2(a[0], a[1]);
            *(float2*)(g_Bu + (size_t)(r0 + 8) * N2 + col) = make_float2(a[2], a[3]);
        }
    }
    #undef G1_LDG
    #undef G1_STS
}

// ---------------- scan 1: chunk carries (64 blocks, warp-per-chunk) ----------
__global__ __launch_bounds__(256) void k_scan1(const float* __restrict__ Lur,
                                               const float* __restrict__ Lim,
                                               const float* __restrict__ logD) {
    int gw = blockIdx.x * 8 + (threadIdx.x >> 5);
    int lane = threadIdx.x & 31;
    int b = gw >> 7, c = gw & (NCH - 1);
    float lbr, lbi, ar, ai;
    lam_bar(Lur, Lim, logD, lane, lbr, lbi, ar, ai);
    size_t base = ((size_t)b * SEQL + (size_t)c * SCHUNK) * N2;
    float xr = 0.f, xi = 0.f;
    for (int i = 0; i < SCHUNK; ++i) {
        size_t off = base + (size_t)i * N2;
        float br = g_Bu[off + lane];
        float bi = g_Bu[off + 32 + lane];
        float nr = fmaf(lbr, xr, fmaf(-lbi, xi, br));
        float ni = fmaf(lbr, xi, fmaf( lbi, xr, bi));
        xr = nr; xi = ni;
    }
    int co = (b * NCH + c) * N2;
    g_car[co + lane]      = xr;
    g_car[co + 32 + lane] = xi;
}

// ---------------- scan 2: prefix with smem-staged carries ----------------
__global__ __launch_bounds__(256) void k_scan2(const float* __restrict__ Lur,
                                               const float* __restrict__ Lim,
                                               const float* __restrict__ logD) {
    __shared__ float s_car[NCH * N2];   // 32 KB
    __shared__ float s_pre[NCH * N2];   // 32 KB
    int tid = threadIdx.x;
    int lane = tid & 31;
    int b = blockIdx.x;

    const float4* src = (const float4*)(g_car + (size_t)b * NCH * N2);
    #pragma unroll
    for (int i = 0; i < (NCH * N2 / 4) / 256; ++i)
        ((float4*)s_car)[tid + 256 * i] = src[tid + 256 * i];
    __syncthreads();

    if (tid < 32) {
        float lbr, lbi, ar, ai;
        lam_bar(Lur, Lim, logD, lane, lbr, lbi, ar, ai);
        float erS = expf((float)SCHUNK * ar);
        float aS  = (float)SCHUNK * ai;
        float lbSr = erS * cosf(aS);
        float lbSi = erS * sinf(aS);
        float Pr = 0.f, Pi = 0.f;
        for (int c = 0; c < NCH; ++c) {
            s_pre[c * N2 + lane]      = Pr;
            s_pre[c * N2 + 32 + lane] = Pi;
            float cr = s_car[c * N2 + lane];
            float ci = s_car[c * N2 + 32 + lane];
            float nr = fmaf(lbSr, Pr, fmaf(-lbSi, Pi, cr));
            float ni = fmaf(lbSr, Pi, fmaf( lbSi, Pr, ci));
            Pr = nr; Pi = ni;
        }
    }
    __syncthreads();

    float4* dst = (float4*)(g_pre + (size_t)b * NCH * N2);
    #pragma unroll
    for (int i = 0; i < (NCH * N2 / 4) / 256; ++i)
        dst[tid + 256 * i] = ((const float4*)s_pre)[tid + 256 * i];
}

// ---------------- scan 3: re-scan + fixup, emit bf16 hi/lo X ----------------
__global__ __launch_bounds__(256) void k_scan3(const float* __restrict__ Lur,
                                               const float* __restrict__ Lim,
                                               const float* __restrict__ logD) {
    int gw = blockIdx.x * 8 + (threadIdx.x >> 5);
    int lane = threadIdx.x & 31;
    int b = gw >> 7, c = gw & (NCH - 1);
    float lbr, lbi, ar, ai;
    lam_bar(Lur, Lim, logD, lane, lbr, lbi, ar, ai);
    int po = (b * NCH + c) * N2;
    float Pr = g_pre[po + lane], Pi = g_pre[po + 32 + lane];
    float pr = lbr, pi = lbi;       // lbar^(i+1)
    size_t base = ((size_t)b * SEQL + (size_t)c * SCHUNK) * N2;
    float xr = 0.f, xi = 0.f;
    for (int i = 0; i < SCHUNK; ++i) {
        size_t off = base + (size_t)i * N2;
        float br = g_Bu[off + lane];
        float bi = g_Bu[off + 32 + lane];
        float nr = fmaf(lbr, xr, fmaf(-lbi, xi, br));
        float ni = fmaf(lbr, xi, fmaf( lbi, xr, bi));
        xr = nr; xi = ni;
        float fxr = fmaf(pr, Pr, fmaf(-pi, Pi, xr));
        float fxi = fmaf(pr, Pi, fmaf( pi, Pr, xi));
        uint16_t hr, lr, hi_, li_;
        cvt_hl(fxr, hr, lr);
        cvt_hl(fxi, hi_, li_);
        g_Xh[off + lane]      = *(__nv_bfloat16*)&hr;
        g_Xh[off + 32 + lane] = *(__nv_bfloat16*)&hi_;
        g_Xl[off + lane]      = *(__nv_bfloat16*)&lr;
        g_Xl[off + 32 + lane] = *(__nv_bfloat16*)&li_;
        float npr = pr * lbr - pi * lbi;
        float npi = pr * lbi + pi * lbr;
        pr = npr; pi = npi;
    }
}

// ---------------- GEMM2 (round-11 proven: coalesced smem-staged epilogue) ----
#define G2_PITCH 132
#define G2_SMEM  (128 * G2_PITCH * 4)   // 67584
__global__ __launch_bounds__(256) void k_gemm2(const float* __restrict__ u,
                                               const float* __restrict__ Dv,
                                               float* __restrict__ y) {
    extern __shared__ char smem[];
    char* pAh = smem;
    char* pAl = smem + 16384;
    char* pBh = smem + 32768;
    char* pBl = smem + 49152;
    int tid = threadIdx.x;
    int lane = tid & 31, g = lane >> 2, tig = lane & 3;
    int w = tid >> 5, wm = w >> 1, wn = w & 1;
    int n0 = blockIdx.x * 128;
    int m0 = blockIdx.y * 128;

    #pragma unroll
    for (int i = 0; i < 4; ++i) {
        int task = tid + 256 * i;
        int row = task >> 3, kp = task & 7;
        size_t goff = ((size_t)(m0 + row) * N2 + kp * 8) * 2;
        int off = kp * 2048 + ((row ^ kp) << 4);
        *(uint4*)(pAh + off) = *(const uint4*)((const char*)g_Xh + goff);
        *(uint4*)(pAl + off) = *(const uint4*)((const char*)g_Xl + goff);
    }
    #pragma unroll
    for (int i = 0; i < 4; ++i) {
        int task = tid + 256 * i;
        int n = task >> 3, kp = task & 7;
        size_t goff = ((size_t)(n0 + n) * N2 + kp * 8) * 2;
        int off = kp * 2048 + ((n ^ kp) << 4);
        *(uint4*)(pBh + off) = *(const uint4*)((const char*)g_W2h + goff);
        *(uint4*)(pBl + off) = *(const uint4*)((const char*)g_W2l + goff);
    }
    __syncthreads();

    float acc[2][8][4];
    #pragma unroll
    for (int mt = 0; mt < 2; ++mt)
        #pragma unroll
        for (int f = 0; f < 8; ++f)
            #pragma unroll
            for (int i = 0; i < 4; ++i) acc[mt][f][i] = 0.f;

    uint32_t aBh = smem_u32(pBh), aBl = smem_u32(pBl);
    uint32_t aAh = smem_u32(pAh), aAl = smem_u32(pAl);

    #pragma unroll
    for (int ks = 0; ks < 4; ++ks) {
        int p = ks * 2;
        uint32_t ah0[4], ah1[4], al0[4], al1[4];
        ldsm4(aAh + lmoff(p, wm * 32,      lane, 2048), ah0);
        ldsm4(aAh + lmoff(p, wm * 32 + 16, lane, 2048), ah1);
        ldsm4(aAl + lmoff(p, wm * 32,      lane, 2048), al0);
        ldsm4(aAl + lmoff(p, wm * 32 + 16, lane, 2048), al1);
        uint32_t bh[16], bl[16];
        #pragma unroll
        for (int s = 0; s < 4; ++s) {
            ldsm4(aBh + lmoff(p, wn * 64 + s * 16, lane, 2048), bh + 4 * s);
            ldsm4(aBl + lmoff(p, wn * 64 + s * 16, lane, 2048), bl + 4 * s);
        }
        #pragma unroll
        for (int f = 0; f < 8; ++f) {
            int q = (f >> 1) * 4 + (f & 1);
            uint32_t bfh[2] = { bh[q], bh[q + 2] };
            uint32_t bfl[2] = { bl[q], bl[q + 2] };
            mma16816(acc[0][f], ah0, bfh);
            mma16816(acc[0][f], ah0, bfl);
            mma16816(acc[0][f], al0, bfh);
            mma16816(acc[1][f], ah1, bfh);
            mma16816(acc[1][f], ah1, bfl);
            mma16816(acc[1][f], al1, bfh);
        }
    }

    // epilogue: stage acc in smem, then fully coalesced y writes
    __syncthreads();
    float* stg = (float*)smem;
    #pragma unroll
    for (int f = 0; f < 8; ++f) {
        int col = wn * 64 + f * 8 + 2 * tig;
        #pragma unroll
        for (int mt = 0; mt < 2; ++mt) {
            int r0 = wm * 32 + mt * 16 + g;
            float* a = acc[mt][f];
            *(float2*)(stg + r0 * G2_PITCH + col)       = make_float2(a[0], a[1]);
            *(float2*)(stg + (r0 + 8) * G2_PITCH + col) = make_float2(a[2], a[3]);
        }
    }
    __syncthreads();
    {
        float4 dv = *(const float4*)(Dv + n0 + lane * 4);
        int rbase = w * 16;
        #pragma unroll
        for (int r = 0; r < 16; ++r) {
            int row = rbase + r;
            float4 a = *(const float4*)(stg + row * G2_PITCH + lane * 4);
            size_t o = (size_t)(m0 + row) * DMODEL + n0 + lane * 4;
            float4 uu = *(const float4*)(u + o);
            float4 out;
            out.x = a.x + dv.x * uu.x;
            out.y = a.y + dv.y * uu.y;
            out.z = a.z + dv.z * uu.z;
            out.w = a.w + dv.w * uu.w;
            *(float4*)(y + o) = out;
        }
    }
}

// ---------------- launch ----------------
extern "C" void kernel_launch(void* const* d_in, const int* in_sizes, int n_in,
                              void* d_out, int out_size) {
    const float* u    = (const float*)d_in[0];
    const float* Lur  = (const float*)d_in[1];
    const float* Lim  = (const float*)d_in[2];
    const float* Bre  = (const float*)d_in[3];
    const float* Bim  = (const float*)d_in[4];
    const float* Cre  = (const float*)d_in[5];
    const float* Cim  = (const float*)d_in[6];
    const float* Dv   = (const float*)d_in[7];
    const float* logD = (const float*)d_in[8];
    float* y = (float*)d_out;

    const int g1_bytes = 2 * G1_STAGE;   // 65536
    const int g2_bytes = G2_SMEM;        // 67584
    cudaFuncSetAttribute(k_gemm1, cudaFuncAttributeMaxDynamicSharedMemorySize,
                         g1_bytes);
    cudaFuncSetAttribute(k_gemm2, cudaFuncAttributeMaxDynamicSharedMemorySize,
                         g2_bytes);

    k_wprep<<<128, 256>>>(Lur, Lim, logD, Bre, Bim, Cre, Cim);
    k_gemm1<<<MTOT / 64, 128, g1_bytes>>>(u);
    k_scan1<<<(BATCH * NCH) / 8, 256>>>(Lur, Lim, logD);
    k_scan2<<<BATCH, 256>>>(Lur, Lim, logD);
    k_scan3<<<(BATCH * NCH) / 8, 256>>>(Lur, Lim, logD);
    k_gemm2<<<dim3(DMODEL / 128, MTOT / 128), 256, g2_bytes>>>(u, Dv, y);
}

// round 16
// speedup vs baseline: 1.0460x; 1.0460x over previous
#include <cuda_runtime.h>
#include <cuda_bf16.h>
#include <cstdint>

#define BATCH   4
#define SEQL    4096
#define DMODEL  2048
#define HALF    32
#define N2      64
#define MTOT    (BATCH*SEQL)
#define SCHUNK  32               // scan chunk length
#define NCH     (SEQL/SCHUNK)    // 128 chunks per batch

// ---------------- scratch ----------------
__device__ __nv_bfloat16 g_W1h[N2 * DMODEL];   // [j][d]  B operand of GEMM1
__device__ __nv_bfloat16 g_W1l[N2 * DMODEL];
__device__ __nv_bfloat16 g_W2h[DMODEL * N2];   // [d][j]  B operand of GEMM2
__device__ __nv_bfloat16 g_W2l[DMODEL * N2];
__device__ float g_Bu[MTOT * N2];
__device__ __nv_bfloat16 g_Xh[MTOT * N2];      // corrected X, bf16 hi
__device__ __nv_bfloat16 g_Xl[MTOT * N2];      // corrected X, bf16 lo
__device__ float g_car[BATCH * NCH * N2];      // chunk carries
__device__ float g_pre[BATCH * NCH * N2];      // exclusive chunk prefixes

// ---------------- helpers ----------------
__device__ __forceinline__ uint32_t smem_u32(const void* p) {
    uint32_t a;
    asm("{ .reg .u64 t; cvta.to.shared.u64 t, %1; cvt.u32.u64 %0, t; }"
        : "=r"(a) : "l"(p));
    return a;
}

__device__ __forceinline__ void cvt_hl(float x, uint16_t& h, uint16_t& l) {
    __nv_bfloat16 hb = __float2bfloat16_rn(x);
    float r = x - __bfloat162float(hb);
    __nv_bfloat16 lb = __float2bfloat16_rn(r);
    h = *(uint16_t*)&hb;
    l = *(uint16_t*)&lb;
}

// paired split: 2 floats -> packed bf16x2 hi + packed bf16x2 lo
__device__ __forceinline__ void cvt_hl2(float x0, float x1,
                                        uint32_t& h, uint32_t& l) {
    uint32_t hp;
    asm("cvt.rn.bf16x2.f32 %0, %1, %2;" : "=r"(hp) : "f"(x1), "f"(x0));
    float f0 = __uint_as_float(hp << 16);
    float f1 = __uint_as_float(hp & 0xffff0000u);
    float r0 = x0 - f0;
    float r1 = x1 - f1;
    asm("cvt.rn.bf16x2.f32 %0, %1, %2;" : "=r"(l) : "f"(r1), "f"(r0));
    h = hp;
}

__device__ __forceinline__ void cvt8(const float4& v0, const float4& v1,
                                     uint4& h, uint4& l) {
    cvt_hl2(v0.x, v0.y, h.x, l.x);
    cvt_hl2(v0.z, v0.w, h.y, l.y);
    cvt_hl2(v1.x, v1.y, h.z, l.z);
    cvt_hl2(v1.z, v1.w, h.w, l.w);
}

__device__ __forceinline__ void mma16816(float* c, const uint32_t* a,
                                         const uint32_t* b) {
    asm volatile(
        "mma.sync.aligned.m16n8k16.row.col.f32.bf16.bf16.f32 "
        "{%0,%1,%2,%3}, {%4,%5,%6,%7}, {%8,%9}, {%0,%1,%2,%3};"
        : "+f"(c[0]), "+f"(c[1]), "+f"(c[2]), "+f"(c[3])
        : "r"(a[0]), "r"(a[1]), "r"(a[2]), "r"(a[3]), "r"(b[0]), "r"(b[1]));
}

__device__ __forceinline__ void ldsm4(uint32_t addr, uint32_t* r) {
    asm volatile(
        "ldmatrix.sync.aligned.m8n8.x4.shared.b16 {%0,%1,%2,%3}, [%4];"
        : "=r"(r[0]), "=r"(r[1]), "=r"(r[2]), "=r"(r[3]) : "r"(addr));
}

// Panels: kp holds 8 k-values; 16B per row; XOR(row, kp) swizzle.
__device__ __forceinline__ uint32_t lmoff(int p, int rb, int lane, int psz) {
    int pp = p + (lane >> 4);
    int row = rb + (lane & 15);
    return (uint32_t)(pp * psz + (((row ^ (pp & 7)) << 4)));
}

// per-state discrete params
__device__ __forceinline__ void lam_bar(const float* Lur, const float* Lim,
                                        const float* logD, int n,
                                        float& lbr, float& lbi,
                                        float& ar, float& ai) {
    float x   = Lur[n];
    float sp  = (x > 20.f) ? x : log1pf(expf(x));
    float lre = -(sp + 1e-4f + 0.01f);
    float lim = Lim[n];
    float dt  = expf(logD[n]);
    ar = lre * dt; ai = lim * dt;
    float er = expf(ar);
    lbr = er * cosf(ai);
    lbi = er * sinf(ai);
}

// ---------------- fused weight prep ----------------
__global__ void k_wprep(const float* __restrict__ Lur,
                        const float* __restrict__ Lim,
                        const float* __restrict__ logD,
                        const float* __restrict__ Bre,
                        const float* __restrict__ Bim,
                        const float* __restrict__ Cre,
                        const float* __restrict__ Cim) {
    __shared__ float s_sre[HALF], s_sim[HALF];
    if (threadIdx.x < HALF) {
        int n = threadIdx.x;
        float lbr, lbi, ar, ai;
        lam_bar(Lur, Lim, logD, n, lbr, lbi, ar, ai);
        float x   = Lur[n];
        float sp  = (x > 20.f) ? x : log1pf(expf(x));
        float lre = -(sp + 1e-4f + 0.01f);
        float lim = Lim[n];
        float den = lre * lre + lim * lim;
        float nr = lbr - 1.f, ni = lbi;
        s_sre[n] = (nr * lre + ni * lim) / den;
        s_sim[n] = (ni * lre - nr * lim) / den;
    }
    __syncthreads();
    const int total = N2 * DMODEL;
    for (int idx = blockIdx.x * blockDim.x + threadIdx.x; idx < total;
         idx += gridDim.x * blockDim.x) {
        {
            int j = idx >> 11;
            int d = idx & 2047;
            int n = j & 31;
            float br = Bre[n * DMODEL + d], bi = Bim[n * DMODEL + d];
            float v = (j < 32) ? (s_sre[n] * br - s_sim[n] * bi)
                               : (s_sre[n] * bi + s_sim[n] * br);
            uint16_t h, l;
            cvt_hl(v, h, l);
            g_W1h[idx] = *(__nv_bfloat16*)&h;
            g_W1l[idx] = *(__nv_bfloat16*)&l;
        }
        {
            int d = idx >> 6;
            int j = idx & 63;
            float v = (j < 32) ? (2.f * Cre[d * HALF + j])
                               : (-2.f * Cim[d * HALF + (j - 32)]);
            uint16_t h, l;
            cvt_hl(v, h, l);
            g_W2h[idx] = *(__nv_bfloat16*)&h;
            g_W2l[idx] = *(__nv_bfloat16*)&l;
        }
    }
}

// ---------------- GEMM1 (round-8/14 proven) ----------------
#define G1_STAGE 49152
__global__ __launch_bounds__(256) void k_gemm1(const float* __restrict__ u) {
    extern __shared__ char smem[];
    int tid = threadIdx.x;
    int lane = tid & 31, g = lane >> 2, tig = lane & 3;
    int w = tid >> 5, wm = w >> 1, wn = w & 1;
    int m0 = blockIdx.x * 128;

    float acc[2][4][4];
    #pragma unroll
    for (int mt = 0; mt < 2; ++mt)
        #pragma unroll
        for (int f = 0; f < 4; ++f)
            #pragma unroll
            for (int i = 0; i < 4; ++i) acc[mt][f][i] = 0.f;

    uint32_t oAh0[4], oAh1[4], oAl0[4], oAl1[4];
    uint32_t oBh0[4], oBh1[4], oBl0[4], oBl1[4];
    #pragma unroll
    for (int ks = 0; ks < 4; ++ks) {
        int p = ks * 2;
        oAh0[ks] =         lmoff(p, wm * 32,      lane, 2048);
        oAh1[ks] =         lmoff(p, wm * 32 + 16, lane, 2048);
        oAl0[ks] = 16384 + lmoff(p, wm * 32,      lane, 2048);
        oAl1[ks] = 16384 + lmoff(p, wm * 32 + 16, lane, 2048);
        oBh0[ks] = 32768 + lmoff(p, wn * 32,      lane, 1024);
        oBh1[ks] = 32768 + lmoff(p, wn * 32 + 16, lane, 1024);
        oBl0[ks] = 40960 + lmoff(p, wn * 32,      lane, 1024);
        oBl1[ks] = 40960 + lmoff(p, wn * 32 + 16, lane, 1024);
    }
    uint32_t sb0 = smem_u32(smem);
    uint32_t sb1 = sb0 + G1_STAGE;

    float4 ru[4][2];
    uint4 rwh[2], rwl[2];

    #define G1_LDG(kb)                                                        \
        _Pragma("unroll")                                                     \
        for (int i = 0; i < 4; ++i) {                                         \
            int task = tid + 256 * i;                                         \
            int row = task >> 3, kp = task & 7;                               \
            const float* s = u + (size_t)(m0 + row) * DMODEL + (kb) + kp * 8; \
            ru[i][0] = *(const float4*)s;                                     \
            ru[i][1] = *(const float4*)(s + 4);                               \
        }                                                                     \
        _Pragma("unroll")                                                     \
        for (int i = 0; i < 2; ++i) {                                         \
            int task = tid + 256 * i;                                         \
            int n = task >> 3, kp = task & 7;                                 \
            size_t off = ((size_t)n * DMODEL + (kb) + kp * 8) * 2;            \
            rwh[i] = *(const uint4*)((const char*)g_W1h + off);               \
            rwl[i] = *(const uint4*)((const char*)g_W1l + off);               \
        }

    #define G1_STS(sbase)                                                     \
        _Pragma("unroll")                                                     \
        for (int i = 0; i < 4; ++i) {                                         \
            int task = tid + 256 * i;                                         \
            int row = task >> 3, kp = task & 7;                               \
            uint4 h, l;                                                       \
            cvt8(ru[i][0], ru[i][1], h, l);                                   \
            int off = kp * 2048 + ((row ^ kp) << 4);                          \
            *(uint4*)((sbase) + off) = h;                                     \
            *(uint4*)((sbase) + 16384 + off) = l;                             \
        }                                                                     \
        _Pragma("unroll")                                                     \
        for (int i = 0; i < 2; ++i) {                                         \
            int task = tid + 256 * i;                                         \
            int n = task >> 3, kp = task & 7;                                 \
            int off = kp * 1024 + ((n ^ kp) << 4);                            \
            *(uint4*)((sbase) + 32768 + off) = rwh[i];                        \
            *(uint4*)((sbase) + 40960 + off) = rwl[i];                        \
        }

    G1_LDG(0);
    G1_STS(smem);
    G1_LDG(64);
    __syncthreads();

    for (int kt = 0; kt < DMODEL / 64; ++kt) {
        if (kt + 1 < DMODEL / 64) {
            char* nst = smem + ((kt + 1) & 1) * G1_STAGE;
            G1_STS(nst);
        }
        if (kt + 2 < DMODEL / 64) {
            G1_LDG((kt + 2) * 64);
        }
        uint32_t sb = (kt & 1) ? sb1 : sb0;
        #pragma unroll
        for (int ks = 0; ks < 4; ++ks) {
            uint32_t ah0[4], ah1[4], al0[4], al1[4];
            ldsm4(sb + oAh0[ks], ah0);
            ldsm4(sb + oAh1[ks], ah1);
            ldsm4(sb + oAl0[ks], al0);
            ldsm4(sb + oAl1[ks], al1);
            uint32_t bh[8], bl[8];
            ldsm4(sb + oBh0[ks], bh);
            ldsm4(sb + oBh1[ks], bh + 4);
            ldsm4(sb + oBl0[ks], bl);
            ldsm4(sb + oBl1[ks], bl + 4);
            #pragma unroll
            for (int f = 0; f < 4; ++f) {
                int q = (f >> 1) * 4 + (f & 1);
                uint32_t bfh[2] = { bh[q], bh[q + 2] };
                uint32_t bfl[2] = { bl[q], bl[q + 2] };
                mma16816(acc[0][f], ah0, bfh);
                mma16816(acc[0][f], ah0, bfl);
                mma16816(acc[0][f], al0, bfh);
                mma16816(acc[1][f], ah1, bfh);
                mma16816(acc[1][f], ah1, bfl);
                mma16816(acc[1][f], al1, bfh);
            }
        }
        __syncthreads();
    }
    #pragma unroll
    for (int mt = 0; mt < 2; ++mt) {
        int r0 = m0 + wm * 32 + mt * 16 + g;
        #pragma unroll
        for (int f = 0; f < 4; ++f) {
            int col = wn * 32 + f * 8 + 2 * tig;
            float* a = acc[mt][f];
            *(float2*)(g_Bu + (size_t)r0 * N2 + col)       = make_float2(a[0], a[1]);
            *(float2*)(g_Bu + (size_t)(r0 + 8) * N2 + col) = make_float2(a[2], a[3]);
        }
    }
    #undef G1_LDG
    #undef G1_STS
}

// ---------------- scan 1: chunk carries (64 blocks, warp-per-chunk) ----------
__global__ __launch_bounds__(256) void k_scan1(const float* __restrict__ Lur,
                                               const float* __restrict__ Lim,
                                               const float* __restrict__ logD) {
    int gw = blockIdx.x * 8 + (threadIdx.x >> 5);
    int lane = threadIdx.x & 31;
    int b = gw >> 7, c = gw & (NCH - 1);
    float lbr, lbi, ar, ai;
    lam_bar(Lur, Lim, logD, lane, lbr, lbi, ar, ai);
    size_t base = ((size_t)b * SEQL + (size_t)c * SCHUNK) * N2;
    float xr = 0.f, xi = 0.f;
    for (int i = 0; i < SCHUNK; ++i) {
        size_t off = base + (size_t)i * N2;
        float br = g_Bu[off + lane];
        float bi = g_Bu[off + 32 + lane];
        float nr = fmaf(lbr, xr, fmaf(-lbi, xi, br));
        float ni = fmaf(lbr, xi, fmaf( lbi, xr, bi));
        xr = nr; xi = ni;
    }
    int co = (b * NCH + c) * N2;
    g_car[co + lane]      = xr;
    g_car[co + 32 + lane] = xi;
}

// ---------------- scan 2: prefix with smem-staged carries ----------------
__global__ __launch_bounds__(256) void k_scan2(const float* __restrict__ Lur,
                                               const float* __restrict__ Lim,
                                               const float* __restrict__ logD) {
    __shared__ float s_car[NCH * N2];   // 32 KB
    __shared__ float s_pre[NCH * N2];   // 32 KB
    int tid = threadIdx.x;
    int lane = tid & 31;
    int b = blockIdx.x;

    const float4* src = (const float4*)(g_car + (size_t)b * NCH * N2);
    #pragma unroll
    for (int i = 0; i < (NCH * N2 / 4) / 256; ++i)
        ((float4*)s_car)[tid + 256 * i] = src[tid + 256 * i];
    __syncthreads();

    if (tid < 32) {
        float lbr, lbi, ar, ai;
        lam_bar(Lur, Lim, logD, lane, lbr, lbi, ar, ai);
        float erS = expf((float)SCHUNK * ar);
        float aS  = (float)SCHUNK * ai;
        float lbSr = erS * cosf(aS);
        float lbSi = erS * sinf(aS);
        float Pr = 0.f, Pi = 0.f;
        for (int c = 0; c < NCH; ++c) {
            s_pre[c * N2 + lane]      = Pr;
            s_pre[c * N2 + 32 + lane] = Pi;
            float cr = s_car[c * N2 + lane];
            float ci = s_car[c * N2 + 32 + lane];
            float nr = fmaf(lbSr, Pr, fmaf(-lbSi, Pi, cr));
            float ni = fmaf(lbSr, Pi, fmaf( lbSi, Pr, ci));
            Pr = nr; Pi = ni;
        }
    }
    __syncthreads();

    float4* dst = (float4*)(g_pre + (size_t)b * NCH * N2);
    #pragma unroll
    for (int i = 0; i < (NCH * N2 / 4) / 256; ++i)
        dst[tid + 256 * i] = ((const float4*)s_pre)[tid + 256 * i];
}

// ---------------- scan 3: re-scan + fixup, emit bf16 hi/lo X ----------------
__global__ __launch_bounds__(256) void k_scan3(const float* __restrict__ Lur,
                                               const float* __restrict__ Lim,
                                               const float* __restrict__ logD) {
    int gw = blockIdx.x * 8 + (threadIdx.x >> 5);
    int lane = threadIdx.x & 31;
    int b = gw >> 7, c = gw & (NCH - 1);
    float lbr, lbi, ar, ai;
    lam_bar(Lur, Lim, logD, lane, lbr, lbi, ar, ai);
    int po = (b * NCH + c) * N2;
    float Pr = g_pre[po + lane], Pi = g_pre[po + 32 + lane];
    float pr = lbr, pi = lbi;       // lbar^(i+1)
    size_t base = ((size_t)b * SEQL + (size_t)c * SCHUNK) * N2;
    float xr = 0.f, xi = 0.f;
    for (int i = 0; i < SCHUNK; ++i) {
        size_t off = base + (size_t)i * N2;
        float br = g_Bu[off + lane];
        float bi = g_Bu[off + 32 + lane];
        float nr = fmaf(lbr, xr, fmaf(-lbi, xi, br));
        float ni = fmaf(lbr, xi, fmaf( lbi, xr, bi));
        xr = nr; xi = ni;
        float fxr = fmaf(pr, Pr, fmaf(-pi, Pi, xr));
        float fxi = fmaf(pr, Pi, fmaf( pi, Pr, xi));
        uint16_t hr, lr, hi_, li_;
        cvt_hl(fxr, hr, lr);
        cvt_hl(fxi, hi_, li_);
        g_Xh[off + lane]      = *(__nv_bfloat16*)&hr;
        g_Xh[off + 32 + lane] = *(__nv_bfloat16*)&hi_;
        g_Xl[off + lane]      = *(__nv_bfloat16*)&lr;
        g_Xl[off + 32 + lane] = *(__nv_bfloat16*)&li_;
        float npr = pr * lbr - pi * lbi;
        float npi = pr * lbi + pi * lbr;
        pr = npr; pi = npi;
    }
}

// ---------------- GEMM2: round-11 body + 2 CTAs/SM (regs capped 124) --------
#define G2_PITCH 132
#define G2_SMEM  (128 * G2_PITCH * 4)   // 67584
__global__ __launch_bounds__(256, 2) void k_gemm2(const float* __restrict__ u,
                                                  const float* __restrict__ Dv,
                                                  float* __restrict__ y) {
    extern __shared__ char smem[];
    char* pAh = smem;
    char* pAl = smem + 16384;
    char* pBh = smem + 32768;
    char* pBl = smem + 49152;
    int tid = threadIdx.x;
    int lane = tid & 31, g = lane >> 2, tig = lane & 3;
    int w = tid >> 5, wm = w >> 1, wn = w & 1;
    int n0 = blockIdx.x * 128;
    int m0 = blockIdx.y * 128;

    #pragma unroll
    for (int i = 0; i < 4; ++i) {
        int task = tid + 256 * i;
        int row = task >> 3, kp = task & 7;
        size_t goff = ((size_t)(m0 + row) * N2 + kp * 8) * 2;
        int off = kp * 2048 + ((row ^ kp) << 4);
        *(uint4*)(pAh + off) = *(const uint4*)((const char*)g_Xh + goff);
        *(uint4*)(pAl + off) = *(const uint4*)((const char*)g_Xl + goff);
    }
    #pragma unroll
    for (int i = 0; i < 4; ++i) {
        int task = tid + 256 * i;
        int n = task >> 3, kp = task & 7;
        size_t goff = ((size_t)(n0 + n) * N2 + kp * 8) * 2;
        int off = kp * 2048 + ((n ^ kp) << 4);
        *(uint4*)(pBh + off) = *(const uint4*)((const char*)g_W2h + goff);
        *(uint4*)(pBl + off) = *(const uint4*)((const char*)g_W2l + goff);
    }
    __syncthreads();

    float acc[2][8][4];
    #pragma unroll
    for (int mt = 0; mt < 2; ++mt)
        #pragma unroll
        for (int f = 0; f < 8; ++f)
            #pragma unroll
            for (int i = 0; i < 4; ++i) acc[mt][f][i] = 0.f;

    uint32_t aBh = smem_u32(pBh), aBl = smem_u32(pBl);
    uint32_t aAh = smem_u32(pAh), aAl = smem_u32(pAl);

    #pragma unroll
    for (int ks = 0; ks < 4; ++ks) {
        int p = ks * 2;
        uint32_t ah0[4], ah1[4], al0[4], al1[4];
        ldsm4(aAh + lmoff(p, wm * 32,      lane, 2048), ah0);
        ldsm4(aAh + lmoff(p, wm * 32 + 16, lane, 2048), ah1);
        ldsm4(aAl + lmoff(p, wm * 32,      lane, 2048), al0);
        ldsm4(aAl + lmoff(p, wm * 32 + 16, lane, 2048), al1);
        uint32_t bh[16], bl[16];
        #pragma unroll
        for (int s = 0; s < 4; ++s) {
            ldsm4(aBh + lmoff(p, wn * 64 + s * 16, lane, 2048), bh + 4 * s);
            ldsm4(aBl + lmoff(p, wn * 64 + s * 16, lane, 2048), bl + 4 * s);
        }
        #pragma unroll
        for (int f = 0; f < 8; ++f) {
            int q = (f >> 1) * 4 + (f & 1);
            uint32_t bfh[2] = { bh[q], bh[q + 2] };
            uint32_t bfl[2] = { bl[q], bl[q + 2] };
            mma16816(acc[0][f], ah0, bfh);
            mma16816(acc[0][f], ah0, bfl);
            mma16816(acc[0][f], al0, bfh);
            mma16816(acc[1][f], ah1, bfh);
            mma16816(acc[1][f], ah1, bfl);
            mma16816(acc[1][f], al1, bfh);
        }
    }

    // epilogue: stage acc in smem, then fully coalesced y writes
    __syncthreads();
    float* stg = (float*)smem;
    #pragma unroll
    for (int f = 0; f < 8; ++f) {
        int col = wn * 64 + f * 8 + 2 * tig;
        #pragma unroll
        for (int mt = 0; mt < 2; ++mt) {
            int r0 = wm * 32 + mt * 16 + g;
            float* a = acc[mt][f];
            *(float2*)(stg + r0 * G2_PITCH + col)       = make_float2(a[0], a[1]);
            *(float2*)(stg + (r0 + 8) * G2_PITCH + col) = make_float2(a[2], a[3]);
        }
    }
    __syncthreads();
    {
        float4 dv = *(const float4*)(Dv + n0 + lane * 4);
        int rbase = w * 16;
        #pragma unroll
        for (int r = 0; r < 16; ++r) {
            int row = rbase + r;
            float4 a = *(const float4*)(stg + row * G2_PITCH + lane * 4);
            size_t o = (size_t)(m0 + row) * DMODEL + n0 + lane * 4;
            float4 uu = *(const float4*)(u + o);
            float4 out;
            out.x = a.x + dv.x * uu.x;
            out.y = a.y + dv.y * uu.y;
            out.z = a.z + dv.z * uu.z;
            out.w = a.w + dv.w * uu.w;
            *(float4*)(y + o) = out;
        }
    }
}

// ---------------- launch ----------------
extern "C" void kernel_launch(void* const* d_in, const int* in_sizes, int n_in,
                              void* d_out, int out_size) {
    const float* u    = (const float*)d_in[0];
    const float* Lur  = (const float*)d_in[1];
    const float* Lim  = (const float*)d_in[2];
    const float* Bre  = (const float*)d_in[3];
    const float* Bim  = (const float*)d_in[4];
    const float* Cre  = (const float*)d_in[5];
    const float* Cim  = (const float*)d_in[6];
    const float* Dv   = (const float*)d_in[7];
    const float* logD = (const float*)d_in[8];
    float* y = (float*)d_out;

    const int g1_bytes = 2 * G1_STAGE;   // 98304
    const int g2_bytes = G2_SMEM;        // 67584
    cudaFuncSetAttribute(k_gemm1, cudaFuncAttributeMaxDynamicSharedMemorySize,
                         g1_bytes);
    cudaFuncSetAttribute(k_gemm2, cudaFuncAttributeMaxDynamicSharedMemorySize,
                         g2_bytes);

    k_wprep<<<128, 256>>>(Lur, Lim, logD, Bre, Bim, Cre, Cim);
    k_gemm1<<<MTOT / 128, 256, g1_bytes>>>(u);
    k_scan1<<<(BATCH * NCH) / 8, 256>>>(Lur, Lim, logD);
    k_scan2<<<BATCH, 256>>>(Lur, Lim, logD);
    k_scan3<<<(BATCH * NCH) / 8, 256>>>(Lur, Lim, logD);
    k_gemm2<<<dim3(DMODEL / 128, MTOT / 128), 256, g2_bytes>>>(u, Dv, y);
}